// round 5
// baseline (speedup 1.0000x reference)
#include <cuda_runtime.h>
#include <math.h>

// ---------------- problem constants ----------------
#define DIN     32
#define KLEN    512
#define PDIM    64
#define DMODEL  128
#define NLAYERS 4
#define PLEN    8
#define STRIDE  4
#define DI2     256
#define DSTATE  16
#define DCONV   4
#define DTRANK  8
#define NSEQ    127
#define BATCH   32
#define MROWS   (BATCH*PDIM)     // 2048
#define RTOT    (MROWS*NSEQ)     // 260096

// ---------------- scratch ----------------
__device__ float g_h[BATCH*KLEN*PDIM];
__device__ float g_e[RTOT*DMODEL];
__device__ float g_rstd[RTOT];
__device__ float g_uz[RTOT*2*DI2];
__device__ float g_y[RTOT*DI2];
__device__ float g_val[MROWS];

// ---------------- helpers ----------------
__device__ __forceinline__ float tf32_rna(float v) {
    unsigned u; asm("cvt.rna.tf32.f32 %0, %1;" : "=r"(u) : "f"(v));
    return __uint_as_float(u);
}
__device__ __forceinline__ void mma_tf32(float* d, const unsigned* a, const unsigned* b) {
    asm volatile(
        "mma.sync.aligned.m16n8k8.row.col.f32.tf32.tf32.f32 "
        "{%0,%1,%2,%3}, {%4,%5,%6,%7}, {%8,%9}, {%0,%1,%2,%3};\n"
        : "+f"(d[0]), "+f"(d[1]), "+f"(d[2]), "+f"(d[3])
        : "r"(a[0]), "r"(a[1]), "r"(a[2]), "r"(a[3]), "r"(b[0]), "r"(b[1]));
}

// ---------------- 1. x@proj_w + b, LayerNorm ----------------
__global__ void k_proj_ln(const float* __restrict__ x, const float* __restrict__ pw,
                          const float* __restrict__ pb, const float* __restrict__ lw,
                          const float* __restrict__ lb) {
    int row = blockIdx.x;
    int t = threadIdx.x;
    __shared__ float xs[DIN];
    __shared__ float r1[64], r2[64];
    if (t < DIN) xs[t] = x[row*DIN + t];
    __syncthreads();
    float acc = pb[t];
#pragma unroll
    for (int i = 0; i < DIN; i++) acc = fmaf(xs[i], pw[i*PDIM + t], acc);
    r1[t] = acc; r2[t] = acc*acc;
    __syncthreads();
    for (int o = 32; o; o >>= 1) {
        if (t < o) { r1[t] += r1[t+o]; r2[t] += r2[t+o]; }
        __syncthreads();
    }
    float mu  = r1[0] * (1.f/64.f);
    float var = r2[0] * (1.f/64.f) - mu*mu;
    g_h[row*PDIM + t] = (acc - mu) * rsqrtf(var + 1e-5f) * lw[t] + lb[t];
}

// ---------------- 2. patch embed ----------------
__global__ void k_patch(const float* __restrict__ pw, const float* __restrict__ pb) {
    int n = blockIdx.x, m = blockIdx.y;
    int t = threadIdx.x;
    __shared__ float hv[PLEN];
    int b = m >> 6, pd = m & 63;
    if (t < PLEN) hv[t] = g_h[(b*KLEN + n*STRIDE + t)*PDIM + pd];
    __syncthreads();
    float acc = pb[t];
#pragma unroll
    for (int p = 0; p < PLEN; p++) acc = fmaf(hv[p], pw[p*DMODEL + t], acc);
    g_e[((size_t)m*NSEQ + n)*DMODEL + t] = acc;
}

// ---------------- 3. per-row rms factor ----------------
__global__ void k_rms() {
    int warp = threadIdx.x >> 5, lane = threadIdx.x & 31;
    int r = blockIdx.x*8 + warp;
    const float* p = g_e + (size_t)r*DMODEL;
    float s = 0.f;
#pragma unroll
    for (int i = 0; i < 4; i++) { float v = p[lane + i*32]; s = fmaf(v, v, s); }
#pragma unroll
    for (int o = 16; o; o >>= 1) s += __shfl_xor_sync(0xffffffff, s, o);
    if (lane == 0) g_rstd[r] = rsqrtf(s*(1.f/DMODEL) + 1e-5f);
}

// ---------------- 4. 3xTF32 tensor-core GEMM ----------------
// MODE 0: C[260096,512] = (rms(e)) @ in_w,  K=128
// MODE 1: g_e += g_y @ out_w,               K=256, N=128
template<int MODE>
__global__ __launch_bounds__(256, 2) void k_gemm_tc(const float* __restrict__ W,
                                                    const float* __restrict__ colScale) {
    constexpr int N = (MODE == 0) ? 512 : 128;
    constexpr int K = (MODE == 0) ? 128 : 256;
    const float* __restrict__ A = (MODE == 0) ? g_e : g_y;
    float* __restrict__ C       = (MODE == 0) ? g_uz : g_e;

    __shared__ float AsH[128][20], AsL[128][20];
    __shared__ float BsH[16][72],  BsL[16][72];

    int tid = threadIdx.x;
    int wid = tid >> 5, lane = tid & 31;
    int wm = wid >> 1, wn = wid & 1;          // 4x2 warp grid, warp tile 32x32
    int g = lane >> 2, tig = lane & 3;
    int row0 = blockIdx.y * 128, col0 = blockIdx.x * 64;

    float acc[2][4][4];
#pragma unroll
    for (int mt = 0; mt < 2; mt++)
#pragma unroll
        for (int nt = 0; nt < 4; nt++)
#pragma unroll
            for (int j = 0; j < 4; j++) acc[mt][nt][j] = 0.f;

    for (int k0 = 0; k0 < K; k0 += 16) {
        // A tile 128x16
#pragma unroll
        for (int s = 0; s < 2; s++) {
            int f = tid + s*256;
            int r = f >> 2, kq = (f & 3)*4;
            float4 v4 = *(const float4*)&A[(size_t)(row0 + r)*K + k0 + kq];
            float vv[4] = {v4.x, v4.y, v4.z, v4.w};
            if (MODE == 0) {
                float rs = g_rstd[row0 + r];
#pragma unroll
                for (int j = 0; j < 4; j++) vv[j] *= rs * colScale[k0 + kq + j];
            }
#pragma unroll
            for (int j = 0; j < 4; j++) {
                float hf = tf32_rna(vv[j]);
                AsH[r][kq + j] = hf;
                AsL[r][kq + j] = tf32_rna(vv[j] - hf);
            }
        }
        // B tile 16x64 ([k][n] in smem, pitch 72)
        {
            int kk = tid >> 4, nn = (tid & 15) * 4;
            float4 v4 = *(const float4*)&W[(size_t)(k0 + kk)*N + col0 + nn];
            float vv[4] = {v4.x, v4.y, v4.z, v4.w};
#pragma unroll
            for (int j = 0; j < 4; j++) {
                float hf = tf32_rna(vv[j]);
                BsH[kk][nn + j] = hf;
                BsL[kk][nn + j] = tf32_rna(vv[j] - hf);
            }
        }
        __syncthreads();
#pragma unroll
        for (int ks = 0; ks < 2; ks++) {
            unsigned aH[2][4], aL[2][4], bH[4][2], bL[4][2];
#pragma unroll
            for (int mt = 0; mt < 2; mt++) {
                int rb = wm*32 + mt*16 + g;
                int kc = ks*8 + tig;
                aH[mt][0] = __float_as_uint(AsH[rb  ][kc  ]);
                aH[mt][1] = __float_as_uint(AsH[rb+8][kc  ]);
                aH[mt][2] = __float_as_uint(AsH[rb  ][kc+4]);
                aH[mt][3] = __float_as_uint(AsH[rb+8][kc+4]);
                aL[mt][0] = __float_as_uint(AsL[rb  ][kc  ]);
                aL[mt][1] = __float_as_uint(AsL[rb+8][kc  ]);
                aL[mt][2] = __float_as_uint(AsL[rb  ][kc+4]);
                aL[mt][3] = __float_as_uint(AsL[rb+8][kc+4]);
            }
#pragma unroll
            for (int nt = 0; nt < 4; nt++) {
                int nb = wn*32 + nt*8 + g;
                int kc = ks*8 + tig;
                bH[nt][0] = __float_as_uint(BsH[kc  ][nb]);
                bH[nt][1] = __float_as_uint(BsH[kc+4][nb]);
                bL[nt][0] = __float_as_uint(BsL[kc  ][nb]);
                bL[nt][1] = __float_as_uint(BsL[kc+4][nb]);
            }
#pragma unroll
            for (int mt = 0; mt < 2; mt++)
#pragma unroll
                for (int nt = 0; nt < 4; nt++) {
                    mma_tf32(acc[mt][nt], aH[mt], bH[nt]);
                    mma_tf32(acc[mt][nt], aL[mt], bH[nt]);
                    mma_tf32(acc[mt][nt], aH[mt], bL[nt]);
                }
        }
        __syncthreads();
    }
#pragma unroll
    for (int mt = 0; mt < 2; mt++) {
#pragma unroll
        for (int nt = 0; nt < 4; nt++) {
            int r = row0 + wm*32 + mt*16 + g;
            int c = col0 + wn*32 + nt*8 + tig*2;
            float* p0 = &C[(size_t)r*N + c];
            float* p1 = &C[(size_t)(r+8)*N + c];
            if (MODE == 1) {
                p0[0] += acc[mt][nt][0]; p0[1] += acc[mt][nt][1];
                p1[0] += acc[mt][nt][2]; p1[1] += acc[mt][nt][3];
            } else {
                p0[0] = acc[mt][nt][0]; p0[1] = acc[mt][nt][1];
                p1[0] = acc[mt][nt][2]; p1[1] = acc[mt][nt][3];
            }
        }
    }
}

// ---------------- 5. fused conv+silu + xproj + dt + scan + silu(z) ----------------
__global__ __launch_bounds__(256, 2) void k_mid(
    const float* __restrict__ xw, const float* __restrict__ dtw, const float* __restrict__ dtb,
    const float* __restrict__ cw, const float* __restrict__ cb,
    const float* __restrict__ alog, const float* __restrict__ dp)
{
    __shared__ float xwT[64][40];    // k-tile of xproj_w
    __shared__ float uS[32][260];    // conv+silu output chunk, pitch 260 (conflict-free)
    __shared__ float dbcS[32][40];   // dt(8)|B(16)|C(16)

    int m = blockIdx.x, tid = threadIdx.x;
    int rloc = tid >> 3, cg = tid & 7;

    float w0 = cw[tid*4+0], w1 = cw[tid*4+1], w2 = cw[tid*4+2], w3 = cw[tid*4+3];
    float cbv = cb[tid];
    float dw[8];
#pragma unroll
    for (int k = 0; k < 8; k++) dw[k] = dtw[k*DI2 + tid];
    float db = dtb[tid];
    float A[16];
#pragma unroll
    for (int s = 0; s < 16; s++) A[s] = -__expf(alog[tid*16 + s]);
    float A0 = A[0];
    bool fast = true;
#pragma unroll
    for (int s = 1; s < 16; s++) {
        float tgt = (float)(s+1)*A0;
        if (fabsf(A[s] - tgt) > 1e-4f*fabsf(tgt)) fast = false;
    }
    float Dv = dp[tid];
    float h[16];
#pragma unroll
    for (int s = 0; s < 16; s++) h[s] = 0.f;
    float x0 = 0.f, x1 = 0.f, x2 = 0.f;
    const float* uz = g_uz + (size_t)m*NSEQ*512;
    float* yp = g_y + (size_t)m*NSEQ*DI2;

    for (int n0 = 0; n0 < NSEQ; n0 += 32) {
        int CN = min(32, NSEQ - n0);
        // --- conv + silu ---
        for (int n = 0; n < CN; n++) {
            float x3 = uz[(size_t)(n0+n)*512 + tid];
            float v = fmaf(x0, w0, fmaf(x1, w1, fmaf(x2, w2, fmaf(x3, w3, cbv))));
            uS[n][tid] = v * (1.f/(1.f + __expf(-v)));
            x0 = x1; x1 = x2; x2 = x3;
        }
        // --- xproj 256 -> 40 ---
        float acc5[5] = {0.f, 0.f, 0.f, 0.f, 0.f};
        for (int kb = 0; kb < DI2; kb += 64) {
            __syncthreads();
            for (int i = tid; i < 64*40; i += 256) {
                int kk = i/40, c = i - kk*40;
                xwT[kk][c] = xw[(kb+kk)*40 + c];
            }
            __syncthreads();
            if (rloc < CN) {
#pragma unroll 8
                for (int k = 0; k < 64; k++) {
                    float a = uS[rloc][kb + k];
#pragma unroll
                    for (int u = 0; u < 5; u++) acc5[u] = fmaf(a, xwT[k][cg*5 + u], acc5[u]);
                }
            }
        }
        __syncthreads();
        if (rloc < CN) {
#pragma unroll
            for (int u = 0; u < 5; u++) dbcS[rloc][cg*5 + u] = acc5[u];
        }
        __syncthreads();
        // --- delta + scan + silu(z) ---
        for (int n = 0; n < CN; n++) {
            float sdt = db;
#pragma unroll
            for (int k = 0; k < 8; k++) sdt = fmaf(dbcS[n][k], dw[k], sdt);
            float d = (sdt > 20.f) ? sdt : log1pf(__expf(sdt));
            float u = uS[n][tid];
            float dlu = d*u;
            float accy = 0.f;
            if (fast) {
                float q = __expf(d*A0);
                float p = q;
#pragma unroll
                for (int s = 0; s < 16; s++) {
                    h[s] = fmaf(p, h[s], dlu*dbcS[n][8 + s]);
                    accy = fmaf(h[s], dbcS[n][24 + s], accy);
                    p *= q;
                }
            } else {
#pragma unroll
                for (int s = 0; s < 16; s++) {
                    float dA = __expf(d*A[s]);
                    h[s] = fmaf(dA, h[s], dlu*dbcS[n][8 + s]);
                    accy = fmaf(h[s], dbcS[n][24 + s], accy);
                }
            }
            float z = uz[(size_t)(n0+n)*512 + DI2 + tid];
            float sz = z / (1.f + __expf(-z));
            yp[(size_t)(n0+n)*DI2 + tid] = (accy + u*Dv) * sz;
        }
        __syncthreads();
    }
}

// ---------------- 6. final rms + bb dot ----------------
__global__ void k_final(const float* __restrict__ fnw, const float* __restrict__ bbw,
                        const float* __restrict__ bbb) {
    int m = blockIdx.x, t = threadIdx.x;   // 128 threads
    int w = t >> 5, lane = t & 31;
    __shared__ float rstdS[NSEQ];
    for (int n = w; n < NSEQ; n += 4) {
        const float* p = g_e + ((size_t)m*NSEQ + n)*DMODEL;
        float s = 0.f;
#pragma unroll
        for (int i = 0; i < 4; i++) { float v = p[lane + 32*i]; s = fmaf(v, v, s); }
#pragma unroll
        for (int o = 16; o; o >>= 1) s += __shfl_xor_sync(0xffffffff, s, o);
        if (lane == 0) rstdS[n] = rsqrtf(s*(1.f/DMODEL) + 1e-5f);
    }
    __syncthreads();
    float fn = fnw[t];
    float acc = 0.f;
    const float* ep = g_e + (size_t)m*NSEQ*DMODEL + t;
#pragma unroll 4
    for (int n = 0; n < NSEQ; n++)
        acc = fmaf(ep[(size_t)n*DMODEL]*rstdS[n]*fn, bbw[n*DMODEL + t], acc);
#pragma unroll
    for (int o = 16; o; o >>= 1) acc += __shfl_xor_sync(0xffffffff, acc, o);
    __shared__ float fr[4];
    if (lane == 0) fr[w] = acc;
    __syncthreads();
    if (t == 0) g_val[m] = fr[0] + fr[1] + fr[2] + fr[3] + bbb[0];
}

// ---------------- 7. head ----------------
__global__ void k_head(const float* __restrict__ hw, const float* __restrict__ hb,
                       float* __restrict__ out) {
    int t = threadIdx.x;  // 64
    int b = t >> 1, o = t & 1;
    float s = hb[o];
    for (int pd = 0; pd < 64; pd++) s = fmaf(g_val[b*64 + pd], hw[pd*2 + o], s);
    out[t] = s;
}

// ---------------- launch ----------------
extern "C" void kernel_launch(void* const* d_in, const int* in_sizes, int n_in,
                              void* d_out, int out_size) {
    const float* x       = (const float*)d_in[0];
    const float* proj_w  = (const float*)d_in[1];
    const float* proj_b  = (const float*)d_in[2];
    const float* ln_w    = (const float*)d_in[3];
    const float* ln_b    = (const float*)d_in[4];
    const float* patch_w = (const float*)d_in[5];
    const float* patch_b = (const float*)d_in[6];
    const float* in_w    = (const float*)d_in[7];
    const float* conv_w  = (const float*)d_in[8];
    const float* conv_b  = (const float*)d_in[9];
    const float* xproj_w = (const float*)d_in[10];
    const float* dt_w    = (const float*)d_in[11];
    const float* dt_b    = (const float*)d_in[12];
    const float* A_log   = (const float*)d_in[13];
    const float* Dp      = (const float*)d_in[14];
    const float* out_w   = (const float*)d_in[15];
    const float* norm_w  = (const float*)d_in[16];
    const float* fnorm_w = (const float*)d_in[17];
    const float* bb_w    = (const float*)d_in[18];
    const float* bb_b    = (const float*)d_in[19];
    const float* head_w  = (const float*)d_in[20];
    const float* head_b  = (const float*)d_in[21];

    k_proj_ln<<<BATCH*KLEN, 64>>>(x, proj_w, proj_b, ln_w, ln_b);
    k_patch<<<dim3(NSEQ, MROWS), DMODEL>>>(patch_w, patch_b);

    for (int l = 0; l < NLAYERS; l++) {
        k_rms<<<RTOT/8, 256>>>();
        k_gemm_tc<0><<<dim3(512/64, RTOT/128), 256>>>(in_w + l*DMODEL*2*DI2,
                                                      norm_w + l*DMODEL);
        k_mid<<<MROWS, 256>>>(xproj_w + l*DI2*40, dt_w + l*DTRANK*DI2, dt_b + l*DI2,
                              conv_w + l*DI2*DCONV, conv_b + l*DI2,
                              A_log + l*DI2*DSTATE, Dp + l*DI2);
        k_gemm_tc<1><<<dim3(DMODEL/64, RTOT/128), 256>>>(out_w + l*DI2*DMODEL, nullptr);
    }

    k_final<<<MROWS, DMODEL>>>(fnorm_w, bb_w, bb_b);
    k_head<<<1, 64>>>(head_w, head_b, (float*)d_out);
}

// round 6
// speedup vs baseline: 1.0838x; 1.0838x over previous
#include <cuda_runtime.h>
#include <math.h>

// ---------------- problem constants ----------------
#define DIN     32
#define KLEN    512
#define PDIM    64
#define DMODEL  128
#define NLAYERS 4
#define PLEN    8
#define STRIDE  4
#define DI2     256
#define DSTATE  16
#define DCONV   4
#define DTRANK  8
#define NSEQ    127
#define BATCH   32
#define MROWS   (BATCH*PDIM)     // 2048
#define RTOT    (MROWS*NSEQ)     // 260096

// ---------------- scratch ----------------
__device__ float g_h[BATCH*KLEN*PDIM];
__device__ float g_e[RTOT*DMODEL];
__device__ float g_rstd[RTOT];
__device__ float g_uz[RTOT*2*DI2];
__device__ float g_y[RTOT*DI2];
__device__ float g_val[MROWS];

// ---------------- helpers ----------------
__device__ __forceinline__ float tf32_rna(float v) {
    unsigned u; asm("cvt.rna.tf32.f32 %0, %1;" : "=r"(u) : "f"(v));
    return __uint_as_float(u);
}
__device__ __forceinline__ void mma_tf32(float* d, const unsigned* a, const unsigned* b) {
    asm volatile(
        "mma.sync.aligned.m16n8k8.row.col.f32.tf32.tf32.f32 "
        "{%0,%1,%2,%3}, {%4,%5,%6,%7}, {%8,%9}, {%0,%1,%2,%3};\n"
        : "+f"(d[0]), "+f"(d[1]), "+f"(d[2]), "+f"(d[3])
        : "r"(a[0]), "r"(a[1]), "r"(a[2]), "r"(a[3]), "r"(b[0]), "r"(b[1]));
}

// ---------------- 1. x@proj_w + b, LayerNorm ----------------
__global__ void k_proj_ln(const float* __restrict__ x, const float* __restrict__ pw,
                          const float* __restrict__ pb, const float* __restrict__ lw,
                          const float* __restrict__ lb) {
    int row = blockIdx.x;
    int t = threadIdx.x;
    __shared__ float xs[DIN];
    __shared__ float r1[64], r2[64];
    if (t < DIN) xs[t] = x[row*DIN + t];
    __syncthreads();
    float acc = pb[t];
#pragma unroll
    for (int i = 0; i < DIN; i++) acc = fmaf(xs[i], pw[i*PDIM + t], acc);
    r1[t] = acc; r2[t] = acc*acc;
    __syncthreads();
    for (int o = 32; o; o >>= 1) {
        if (t < o) { r1[t] += r1[t+o]; r2[t] += r2[t+o]; }
        __syncthreads();
    }
    float mu  = r1[0] * (1.f/64.f);
    float var = r2[0] * (1.f/64.f) - mu*mu;
    g_h[row*PDIM + t] = (acc - mu) * rsqrtf(var + 1e-5f) * lw[t] + lb[t];
}

// ---------------- 2. patch embed ----------------
__global__ void k_patch(const float* __restrict__ pw, const float* __restrict__ pb) {
    int n = blockIdx.x, m = blockIdx.y;
    int t = threadIdx.x;
    __shared__ float hv[PLEN];
    int b = m >> 6, pd = m & 63;
    if (t < PLEN) hv[t] = g_h[(b*KLEN + n*STRIDE + t)*PDIM + pd];
    __syncthreads();
    float acc = pb[t];
#pragma unroll
    for (int p = 0; p < PLEN; p++) acc = fmaf(hv[p], pw[p*DMODEL + t], acc);
    g_e[((size_t)m*NSEQ + n)*DMODEL + t] = acc;
}

// ---------------- 3. per-row rms factor ----------------
__global__ void k_rms() {
    int warp = threadIdx.x >> 5, lane = threadIdx.x & 31;
    int r = blockIdx.x*8 + warp;
    const float* p = g_e + (size_t)r*DMODEL;
    float s = 0.f;
#pragma unroll
    for (int i = 0; i < 4; i++) { float v = p[lane + i*32]; s = fmaf(v, v, s); }
#pragma unroll
    for (int o = 16; o; o >>= 1) s += __shfl_xor_sync(0xffffffff, s, o);
    if (lane == 0) g_rstd[r] = rsqrtf(s*(1.f/DMODEL) + 1e-5f);
}

// ---------------- 4. 3xTF32 tensor-core GEMM, block 128x128, warp 64x32 ----------------
// MODE 0: g_uz[260096,512] = (rms(e)) @ in_w, K=128
// MODE 1: g_e  += g_y @ out_w,                K=256, N=128
template<int MODE>
__global__ __launch_bounds__(256, 2) void k_gemm_tc(const float* __restrict__ W,
                                                    const float* __restrict__ colScale) {
    constexpr int N = (MODE == 0) ? 512 : 128;
    constexpr int K = (MODE == 0) ? 128 : 256;
    const float* __restrict__ A = (MODE == 0) ? g_e : g_y;
    float* __restrict__ C       = (MODE == 0) ? g_uz : g_e;

    __shared__ float AsH[128][20], AsL[128][20];
    __shared__ float BsH[16][136], BsL[16][136];

    int tid = threadIdx.x;
    int wid = tid >> 5, lane = tid & 31;
    int wm = wid >> 2, wn = wid & 3;          // 2x4 warp grid, warp tile 64x32
    int g = lane >> 2, tig = lane & 3;
    int row0 = blockIdx.y * 128, col0 = blockIdx.x * 128;

    float acc[4][4][4];
#pragma unroll
    for (int mt = 0; mt < 4; mt++)
#pragma unroll
        for (int nt = 0; nt < 4; nt++)
#pragma unroll
            for (int j = 0; j < 4; j++) acc[mt][nt][j] = 0.f;

    for (int k0 = 0; k0 < K; k0 += 16) {
        // A tile 128x16 (hi/lo)
#pragma unroll
        for (int s = 0; s < 2; s++) {
            int r = (tid >> 2) + s*64, kq = (tid & 3)*4;
            float4 v4 = *(const float4*)&A[(size_t)(row0 + r)*K + k0 + kq];
            float vv[4] = {v4.x, v4.y, v4.z, v4.w};
            if (MODE == 0) {
                float rs = g_rstd[row0 + r];
#pragma unroll
                for (int j = 0; j < 4; j++) vv[j] *= rs * colScale[k0 + kq + j];
            }
#pragma unroll
            for (int j = 0; j < 4; j++) {
                float hf = tf32_rna(vv[j]);
                AsH[r][kq + j] = hf;
                AsL[r][kq + j] = tf32_rna(vv[j] - hf);
            }
        }
        // B tile 16x128 (hi/lo)
#pragma unroll
        for (int s = 0; s < 2; s++) {
            int i = tid + s*256;
            int kk = i >> 5, nn = (i & 31)*4;
            float4 v4 = *(const float4*)&W[(size_t)(k0 + kk)*N + col0 + nn];
            float vv[4] = {v4.x, v4.y, v4.z, v4.w};
#pragma unroll
            for (int j = 0; j < 4; j++) {
                float hf = tf32_rna(vv[j]);
                BsH[kk][nn + j] = hf;
                BsL[kk][nn + j] = tf32_rna(vv[j] - hf);
            }
        }
        __syncthreads();
#pragma unroll
        for (int ks = 0; ks < 2; ks++) {
            int kc = ks*8 + tig;
            unsigned aH[4][4], aL[4][4];
#pragma unroll
            for (int mt = 0; mt < 4; mt++) {
                int rb = wm*64 + mt*16 + g;
                aH[mt][0] = __float_as_uint(AsH[rb  ][kc  ]);
                aH[mt][1] = __float_as_uint(AsH[rb+8][kc  ]);
                aH[mt][2] = __float_as_uint(AsH[rb  ][kc+4]);
                aH[mt][3] = __float_as_uint(AsH[rb+8][kc+4]);
                aL[mt][0] = __float_as_uint(AsL[rb  ][kc  ]);
                aL[mt][1] = __float_as_uint(AsL[rb+8][kc  ]);
                aL[mt][2] = __float_as_uint(AsL[rb  ][kc+4]);
                aL[mt][3] = __float_as_uint(AsL[rb+8][kc+4]);
            }
#pragma unroll
            for (int nt = 0; nt < 4; nt++) {
                int nb = wn*32 + nt*8 + g;
                unsigned bH[2], bL[2];
                bH[0] = __float_as_uint(BsH[kc  ][nb]);
                bH[1] = __float_as_uint(BsH[kc+4][nb]);
                bL[0] = __float_as_uint(BsL[kc  ][nb]);
                bL[1] = __float_as_uint(BsL[kc+4][nb]);
#pragma unroll
                for (int mt = 0; mt < 4; mt++) {
                    mma_tf32(acc[mt][nt], aH[mt], bH);
                    mma_tf32(acc[mt][nt], aL[mt], bH);
                    mma_tf32(acc[mt][nt], aH[mt], bL);
                }
            }
        }
        __syncthreads();
    }
#pragma unroll
    for (int mt = 0; mt < 4; mt++) {
#pragma unroll
        for (int nt = 0; nt < 4; nt++) {
            int r = row0 + wm*64 + mt*16 + g;
            int c = col0 + wn*32 + nt*8 + tig*2;
            float* p0 = &C[(size_t)r*N + c];
            float* p1 = &C[(size_t)(r+8)*N + c];
            if (MODE == 1) {
                p0[0] += acc[mt][nt][0]; p0[1] += acc[mt][nt][1];
                p1[0] += acc[mt][nt][2]; p1[1] += acc[mt][nt][3];
            } else {
                p0[0] = acc[mt][nt][0]; p0[1] = acc[mt][nt][1];
                p1[0] = acc[mt][nt][2]; p1[1] = acc[mt][nt][3];
            }
        }
    }
}

// ---------------- 5. fused conv+silu + xproj + dt + scan + silu(z) ----------------
#define SMEM_MID ((256*40 + 32*260 + 32*40)*4)   // 79360 B dynamic

__global__ __launch_bounds__(256) void k_mid(
    const float* __restrict__ xw, const float* __restrict__ dtw, const float* __restrict__ dtb,
    const float* __restrict__ cw, const float* __restrict__ cb,
    const float* __restrict__ alog, const float* __restrict__ dp)
{
    extern __shared__ float sm[];
    float* xwS  = sm;                   // [256][40] full xproj_w
    float* uS   = sm + 256*40;          // [32][260] conv+silu chunk
    float* dbcS = uS + 32*260;          // [32][40]  dt|B|C

    int m = blockIdx.x, tid = threadIdx.x;
    int rloc = tid >> 3, cg = tid & 7;

    for (int i = tid; i < 256*40; i += 256) xwS[i] = xw[i];

    float w0 = cw[tid*4+0], w1 = cw[tid*4+1], w2 = cw[tid*4+2], w3 = cw[tid*4+3];
    float cbv = cb[tid];
    float dw[8];
#pragma unroll
    for (int k = 0; k < 8; k++) dw[k] = dtw[k*DI2 + tid];
    float db = dtb[tid];
    float A[16];
#pragma unroll
    for (int s = 0; s < 16; s++) A[s] = -__expf(alog[tid*16 + s]);
    float A0 = A[0];
    bool fast = true;
#pragma unroll
    for (int s = 1; s < 16; s++) {
        float tgt = (float)(s+1)*A0;
        if (fabsf(A[s] - tgt) > 1e-4f*fabsf(tgt)) fast = false;
    }
    float Dv = dp[tid];
    float h[16];
#pragma unroll
    for (int s = 0; s < 16; s++) h[s] = 0.f;
    float x0 = 0.f, x1 = 0.f, x2 = 0.f;
    const float* uz = g_uz + (size_t)m*NSEQ*512;
    float* yp = g_y + (size_t)m*NSEQ*DI2;
    __syncthreads();

    for (int n0 = 0; n0 < NSEQ; n0 += 32) {
        // --- conv + silu (fixed trip, guarded -> batched LDGs) ---
#pragma unroll 8
        for (int n = 0; n < 32; n++) {
            if (n0 + n < NSEQ) {
                float x3 = uz[(size_t)(n0+n)*512 + tid];
                float v = fmaf(x0, w0, fmaf(x1, w1, fmaf(x2, w2, fmaf(x3, w3, cbv))));
                uS[n*260 + tid] = v * (1.f/(1.f + __expf(-v)));
                x0 = x1; x1 = x2; x2 = x3;
            }
        }
        __syncthreads();
        // --- xproj 256 -> 40 (weights resident in smem) ---
        if (n0 + rloc < NSEQ) {
            float acc5[5] = {0.f, 0.f, 0.f, 0.f, 0.f};
            const float* ur = uS + rloc*260;
#pragma unroll 4
            for (int k = 0; k < 256; k++) {
                float a = ur[k];
                const float* wr = xwS + k*40 + cg*5;
#pragma unroll
                for (int u = 0; u < 5; u++) acc5[u] = fmaf(a, wr[u], acc5[u]);
            }
#pragma unroll
            for (int u = 0; u < 5; u++) dbcS[rloc*40 + cg*5 + u] = acc5[u];
        }
        __syncthreads();
        // --- delta + scan + silu(z) ---
        for (int n = 0; n < 32; n++) {
            if (n0 + n < NSEQ) {
                const float* dbc = dbcS + n*40;
                float sdt = db;
#pragma unroll
                for (int k = 0; k < 8; k++) sdt = fmaf(dbc[k], dw[k], sdt);
                float d = (sdt > 20.f) ? sdt : log1pf(__expf(sdt));
                float u = uS[n*260 + tid];
                float dlu = d*u;
                float a0 = 0.f, a1 = 0.f, a2 = 0.f, a3 = 0.f;
                if (fast) {
                    float q = __expf(d*A0);
                    float q2 = q*q, q3 = q2*q, q4 = q2*q2;
                    float q8 = q4*q4, q12 = q8*q4;
                    float pl[4] = {q, q2, q3, q4};
                    float pe[4] = {1.f, q4, q8, q12};
#pragma unroll
                    for (int s = 0; s < 16; s++) {
                        float p = pe[s>>2]*pl[s&3];
                        h[s] = fmaf(p, h[s], dlu*dbc[8 + s]);
                        float t = h[s]*dbc[24 + s];
                        if      ((s&3) == 0) a0 += t;
                        else if ((s&3) == 1) a1 += t;
                        else if ((s&3) == 2) a2 += t;
                        else                 a3 += t;
                    }
                } else {
#pragma unroll
                    for (int s = 0; s < 16; s++) {
                        float dA = __expf(d*A[s]);
                        h[s] = fmaf(dA, h[s], dlu*dbc[8 + s]);
                        float t = h[s]*dbc[24 + s];
                        if      ((s&3) == 0) a0 += t;
                        else if ((s&3) == 1) a1 += t;
                        else if ((s&3) == 2) a2 += t;
                        else                 a3 += t;
                    }
                }
                float accy = (a0 + a1) + (a2 + a3);
                float z = uz[(size_t)(n0+n)*512 + DI2 + tid];
                float sz = z / (1.f + __expf(-z));
                yp[(size_t)(n0+n)*DI2 + tid] = (accy + u*Dv) * sz;
            }
        }
        __syncthreads();
    }
}

// ---------------- 6. final rms + bb dot ----------------
__global__ void k_final(const float* __restrict__ fnw, const float* __restrict__ bbw,
                        const float* __restrict__ bbb) {
    int m = blockIdx.x, t = threadIdx.x;   // 128 threads
    int w = t >> 5, lane = t & 31;
    __shared__ float rstdS[NSEQ];
    for (int n = w; n < NSEQ; n += 4) {
        const float* p = g_e + ((size_t)m*NSEQ + n)*DMODEL;
        float s = 0.f;
#pragma unroll
        for (int i = 0; i < 4; i++) { float v = p[lane + 32*i]; s = fmaf(v, v, s); }
#pragma unroll
        for (int o = 16; o; o >>= 1) s += __shfl_xor_sync(0xffffffff, s, o);
        if (lane == 0) rstdS[n] = rsqrtf(s*(1.f/DMODEL) + 1e-5f);
    }
    __syncthreads();
    float fn = fnw[t];
    float acc = 0.f;
    const float* ep = g_e + (size_t)m*NSEQ*DMODEL + t;
#pragma unroll 4
    for (int n = 0; n < NSEQ; n++)
        acc = fmaf(ep[(size_t)n*DMODEL]*rstdS[n]*fn, bbw[n*DMODEL + t], acc);
#pragma unroll
    for (int o = 16; o; o >>= 1) acc += __shfl_xor_sync(0xffffffff, acc, o);
    __shared__ float fr[4];
    if (lane == 0) fr[w] = acc;
    __syncthreads();
    if (t == 0) g_val[m] = fr[0] + fr[1] + fr[2] + fr[3] + bbb[0];
}

// ---------------- 7. head ----------------
__global__ void k_head(const float* __restrict__ hw, const float* __restrict__ hb,
                       float* __restrict__ out) {
    int t = threadIdx.x;  // 64
    int b = t >> 1, o = t & 1;
    float s = hb[o];
    for (int pd = 0; pd < 64; pd++) s = fmaf(g_val[b*64 + pd], hw[pd*2 + o], s);
    out[t] = s;
}

// ---------------- launch ----------------
extern "C" void kernel_launch(void* const* d_in, const int* in_sizes, int n_in,
                              void* d_out, int out_size) {
    const float* x       = (const float*)d_in[0];
    const float* proj_w  = (const float*)d_in[1];
    const float* proj_b  = (const float*)d_in[2];
    const float* ln_w    = (const float*)d_in[3];
    const float* ln_b    = (const float*)d_in[4];
    const float* patch_w = (const float*)d_in[5];
    const float* patch_b = (const float*)d_in[6];
    const float* in_w    = (const float*)d_in[7];
    const float* conv_w  = (const float*)d_in[8];
    const float* conv_b  = (const float*)d_in[9];
    const float* xproj_w = (const float*)d_in[10];
    const float* dt_w    = (const float*)d_in[11];
    const float* dt_b    = (const float*)d_in[12];
    const float* A_log   = (const float*)d_in[13];
    const float* Dp      = (const float*)d_in[14];
    const float* out_w   = (const float*)d_in[15];
    const float* norm_w  = (const float*)d_in[16];
    const float* fnorm_w = (const float*)d_in[17];
    const float* bb_w    = (const float*)d_in[18];
    const float* bb_b    = (const float*)d_in[19];
    const float* head_w  = (const float*)d_in[20];
    const float* head_b  = (const float*)d_in[21];

    cudaFuncSetAttribute(k_mid, cudaFuncAttributeMaxDynamicSharedMemorySize, SMEM_MID);

    k_proj_ln<<<BATCH*KLEN, 64>>>(x, proj_w, proj_b, ln_w, ln_b);
    k_patch<<<dim3(NSEQ, MROWS), DMODEL>>>(patch_w, patch_b);

    for (int l = 0; l < NLAYERS; l++) {
        k_rms<<<RTOT/8, 256>>>();
        k_gemm_tc<0><<<dim3(512/128, RTOT/128), 256>>>(in_w + l*DMODEL*2*DI2,
                                                       norm_w + l*DMODEL);
        k_mid<<<MROWS, 256, SMEM_MID>>>(xproj_w + l*DI2*40, dt_w + l*DTRANK*DI2, dt_b + l*DI2,
                                        conv_w + l*DI2*DCONV, conv_b + l*DI2,
                                        A_log + l*DI2*DSTATE, Dp + l*DI2);
        k_gemm_tc<1><<<dim3(1, RTOT/128), 256>>>(out_w + l*DI2*DMODEL, nullptr);
    }

    k_final<<<MROWS, DMODEL>>>(fnorm_w, bb_w, bb_b);
    k_head<<<1, 64>>>(head_w, head_b, (float*)d_out);
}